// round 12
// baseline (speedup 1.0000x reference)
#include <cuda_runtime.h>
#include <cstdint>

#define DP    512
#define D     500
#define MDIM  250
#define NDIM  250
#define BATCH 1024
#define HDIM  512
#define ITERS 1000
#define SROW  9          // ull per state column (8 rows + pad) -> 2-way store conflicts
#define CLSZ  8          // cluster size (TMA multicast group)
#define STAGES 3
#define CH_K  16         // k-rows per chunk
#define CH_BYTES (CH_K * DP * 4)        // 32768
#define NCHUNK (DP / CH_K)              // 32 per iteration
#define TOTALC (NCHUNK * (ITERS + 1))   // global chunk count

typedef unsigned long long ull;

// ---------------- device scratch ----------------
__device__ float g_P [DP*DP];
__device__ float g_h1[BATCH*HDIM];
__device__ float g_h2[BATCH*HDIM];
__device__ float g_y [BATCH*DP];
__device__ float g_q [BATCH*DP];

// ---------------- helpers ----------------
__device__ __forceinline__ void ffma2(ull &d, ull a, ull b) {
    asm("fma.rn.f32x2 %0, %1, %2, %0;" : "+l"(d) : "l"(a), "l"(b));
}
__device__ __forceinline__ float2 unpk(ull a) {
    float2 f; asm("mov.b64 {%0,%1}, %2;" : "=f"(f.x), "=f"(f.y) : "l"(a)); return f;
}
__device__ __forceinline__ ull dup2(float v) {
    ull d; asm("mov.b64 %0, {%1,%1};" : "=l"(d) : "f"(v)); return d;
}
__device__ __forceinline__ uint32_t smem_u32(const void* p) {
    uint32_t a; asm("{ .reg .u64 t; cvta.to.shared.u64 t, %1; cvt.u32.u64 %0, t; }" : "=r"(a) : "l"(p)); return a;
}
__device__ __forceinline__ uint32_t ctarank() {
    uint32_t r; asm("mov.u32 %0, %%cluster_ctarank;" : "=r"(r)); return r;
}
__device__ __forceinline__ void mbar_init(uint32_t addr, uint32_t cnt) {
    asm volatile("mbarrier.init.shared.b64 [%0], %1;" :: "r"(addr), "r"(cnt) : "memory");
}
__device__ __forceinline__ void mbar_expect_tx(uint32_t addr, uint32_t tx) {
    asm volatile("mbarrier.arrive.expect_tx.shared.b64 _, [%0], %1;" :: "r"(addr), "r"(tx) : "memory");
}
__device__ __forceinline__ void mbar_arrive_rank0(uint32_t local_addr) {
    asm volatile(
        "{ .reg .b32 ra;\n\t"
        "mapa.shared::cluster.u32 ra, %0, 0;\n\t"
        "mbarrier.arrive.shared::cluster.b64 _, [ra]; }"
        :: "r"(local_addr) : "memory");
}
__device__ __forceinline__ void mbar_wait(uint32_t addr, uint32_t parity) {
    uint32_t done;
    asm volatile(
        "{ .reg .pred p;\n\t"
        "mbarrier.try_wait.parity.acquire.cta.shared::cta.b64 p, [%1], %2;\n\t"
        "selp.b32 %0, 1, 0, p; }"
        : "=r"(done) : "r"(addr), "r"(parity) : "memory");
    if (!done) {
        asm volatile(
            "{ .reg .pred P1;\n\t"
            "WL_%=:\n\t"
            "mbarrier.try_wait.parity.acquire.cta.shared::cta.b64 P1, [%0], %1, 0x989680;\n\t"
            "@P1 bra.uni WD_%=;\n\t"
            "bra.uni WL_%=;\n\t"
            "WD_%=: }"
            :: "r"(addr), "r"(parity) : "memory");
    }
}
__device__ __forceinline__ void bulk_mc(uint32_t dst, const void* src, uint32_t bytes,
                                        uint32_t mbar, uint16_t mask) {
    asm volatile(
        "cp.async.bulk.shared::cluster.global.mbarrier::complete_tx::bytes.multicast::cluster"
        " [%0], [%1], %2, [%3], %4;"
        :: "r"(dst), "l"(src), "r"(bytes), "r"(mbar), "h"(mask) : "memory");
}
#define CLUSTER_SYNC() do { \
    asm volatile("barrier.cluster.arrive.aligned;" ::: "memory"); \
    asm volatile("barrier.cluster.wait.aligned;"   ::: "memory"); } while(0)

// ---------------- P = I - (Aaug_inv @ Aaug)^T ----------------
__global__ void computeP(const float* __restrict__ Aaug, const float* __restrict__ Ainv) {
    int idx = blockIdx.x * 256 + threadIdx.x;
    int i = idx & (DP - 1);
    int j = idx >> 9;
    float acc = 0.f;
    if (i < D && j < D) {
        acc = (i == j) ? 1.f : 0.f;
        for (int k = 0; k < MDIM; ++k)
            acc -= Aaug[k * D + i] * Ainv[j * MDIM + k];
    }
    g_P[i * DP + j] = acc;
}

// ---------------- front-end MLP GEMM ----------------
#define FLAG_RELU   1
#define FLAG_TRANSB 2
#define FLAG_CONCAT 4
__global__ void gemm16(const float* __restrict__ A, const float* __restrict__ A2,
                       const float* __restrict__ B, const float* __restrict__ bias,
                       float* __restrict__ C, int K, int Nr, int ldc, int flags) {
    __shared__ float As[16][16];
    __shared__ float Bs[16][17];
    int tx = threadIdx.x, ty = threadIdx.y;
    int m = blockIdx.y * 16 + ty;
    int n = blockIdx.x * 16 + tx;
    float acc = 0.f;
    for (int k0 = 0; k0 < K; k0 += 16) {
        int ka = k0 + tx;
        float av = 0.f;
        if (ka < K) {
            if (flags & FLAG_CONCAT) av = (ka < MDIM) ? A[m * MDIM + ka] : A2[m * MDIM + ka - MDIM];
            else                     av = A[m * K + ka];
        }
        As[ty][tx] = av;
        int kb = k0 + ty;
        float bv = 0.f;
        if (kb < K && n < Nr) bv = (flags & FLAG_TRANSB) ? B[n * K + kb] : B[kb * Nr + n];
        Bs[ty][tx] = bv;
        __syncthreads();
#pragma unroll
        for (int kk = 0; kk < 16; ++kk) acc += As[ty][kk] * Bs[kk][tx];
        __syncthreads();
    }
    if (n < ldc) {
        float v = 0.f;
        if (n < Nr) {
            v = acc + (bias ? bias[n] : 0.f);
            if (flags & FLAG_RELU) v = fmaxf(v, 0.f);
        }
        C[m * ldc + n] = v;
    }
}

// ---------------- persistent iteration kernel (8-CTA multicast P stream) ------
// 128 CTAs (16 clusters x 8) x 256 threads. CTA owns 8 batch rows, ALL 512 cols
// (same decomposition as the 12.46ms R7 kernel: no cross-CTA state exchange).
// P streamed via leader-issued cp.async.bulk multicast: 32KB chunks (16 k-rows),
// 3-stage smem ring, mbarrier pipeline (full: count1+expect_tx per CTA;
// empty: count 64 = 8 warps x 8 CTAs, remote arrives to leader). Lookahead L=2.
// GEMM: warp w -> (ch = w&1 col half, kq = w>>1 k-quarter WITHIN chunk).
// Epilogue identical to R7; y/q live in registers.
#define SDUP_OFF  0
#define RED_OFF   (DP * SROW * 8)                   // 36864
#define PST_OFF   (RED_OFF + 8 * 8 * 256 * 4)       // 36864+65536 = 102400
#define MB_OFF    (PST_OFF + STAGES * CH_BYTES)     // 102400+98304 = 200704
#define SMEM_BYTES (MB_OFF + 64)                    // 200768

__global__ void __launch_bounds__(256, 1) __cluster_dims__(CLSZ, 1, 1)
iterate_kernel(float* __restrict__ out) {
    extern __shared__ char smem[];
    ull*   sdup = (ull*)(smem + SDUP_OFF);          // [512][SROW] dup {s,s}
    float* redf = (float*)(smem + RED_OFF);         // [8 warps][8 rows][256]

    const int tid  = threadIdx.x;
    const int warp = tid >> 5, lane = tid & 31;
    const int ch = warp & 1, kq = warp >> 1;
    const uint32_t rank = ctarank();
    const int rowbase = blockIdx.x * 8;
    const bool mthread = (lane == 0 && warp == 0);
    const bool leader  = (rank == 0);

    const uint32_t sb = smem_u32(smem);
    const uint32_t mb_full  = sb + MB_OFF;          // + st*8
    const uint32_t mb_empty = sb + MB_OFF + 24;     // + st*8

    // ---- init: zero s, init mbars, arm initial expect_tx ----
    for (int i = tid; i < DP * SROW; i += 256) sdup[i] = 0ull;
    if (tid == 0) {
#pragma unroll
        for (int st = 0; st < STAGES; ++st) {
            mbar_init(mb_full + st * 8, 1);
            mbar_init(mb_empty + st * 8, 64);
            mbar_expect_tx(mb_full + st * 8, CH_BYTES);   // arm chunks 0,1,2
        }
    }
    // y/q into registers: row = warp, col j = s*32+lane
    float y_reg[16], q_reg[16], s_reg[16];
    {
        const float* yrow = g_y + (rowbase + warp) * DP;
        const float* qrow = g_q + (rowbase + warp) * DP;
#pragma unroll
        for (int s = 0; s < 16; ++s) {
            y_reg[s] = yrow[s * 32 + lane];
            q_reg[s] = qrow[s * 32 + lane];
            s_reg[s] = 0.f;
        }
    }
    __syncthreads();
    CLUSTER_SYNC();   // all mbars initialized before any multicast lands

    // leader prefill: chunks 0,1 (lookahead L=2)
    int e_st = 0, e_ph = 1;    // empty cursor (init phase 1: first waits pass)
    if (leader && mthread) {
#pragma unroll
        for (int m = 0; m < 2; ++m) {
            mbar_wait(mb_empty + e_st * 8, e_ph);
            bulk_mc(sb + PST_OFF + e_st * CH_BYTES, g_P + m * (CH_K * DP),
                    CH_BYTES, mb_full + e_st * 8, (uint16_t)0xFF);
            if (++e_st == STAGES) { e_st = 0; e_ph ^= 1; }
        }
    }

    const float OMEGA = 1.8f, TWOSIG = 0.2f, INVC = 1.0f / 1.2f;
    int f_st = 0, f_ph = 0;    // full cursor (all threads)

    float* redw = redf + (ch * 4 + kq) * (8 * 256) + lane * 4;

    for (int it = 0; it <= ITERS; ++it) {
        // ================= GEMM over 32 chunks =================
        ull acc[8][4];
#pragma unroll
        for (int r = 0; r < 8; ++r)
#pragma unroll
            for (int p = 0; p < 4; ++p) acc[r][p] = 0ull;

#pragma unroll 1
        for (int c = 0; c < NCHUNK; ++c) {
            mbar_wait(mb_full + f_st * 8, f_ph);
            const char* pchunk = smem + PST_OFF + f_st * CH_BYTES
                               + (ch * 256) * 4 + lane * 16;
#pragma unroll
            for (int u = 0; u < 4; ++u) {
                const int kl = kq * 4 + u;
                const int kg = (c << 4) + kl;
                const ull* sc = sdup + kg * SROW;
                const char* pp = pchunk + kl * (DP * 4);
                ulonglong2 pA = *(const ulonglong2*)pp;
                ulonglong2 pB = *(const ulonglong2*)(pp + 512);
                ull sd0 = sc[0], sd1 = sc[1], sd2 = sc[2], sd3 = sc[3];
                ull sd4 = sc[4], sd5 = sc[5], sd6 = sc[6], sd7 = sc[7];
                ull p0 = pA.x, p1 = pA.y, p2 = pB.x, p3 = pB.y;
                ffma2(acc[0][0], sd0, p0); ffma2(acc[0][1], sd0, p1);
                ffma2(acc[0][2], sd0, p2); ffma2(acc[0][3], sd0, p3);
                ffma2(acc[1][0], sd1, p0); ffma2(acc[1][1], sd1, p1);
                ffma2(acc[1][2], sd1, p2); ffma2(acc[1][3], sd1, p3);
                ffma2(acc[2][0], sd2, p0); ffma2(acc[2][1], sd2, p1);
                ffma2(acc[2][2], sd2, p2); ffma2(acc[2][3], sd2, p3);
                ffma2(acc[3][0], sd3, p0); ffma2(acc[3][1], sd3, p1);
                ffma2(acc[3][2], sd3, p2); ffma2(acc[3][3], sd3, p3);
                ffma2(acc[4][0], sd4, p0); ffma2(acc[4][1], sd4, p1);
                ffma2(acc[4][2], sd4, p2); ffma2(acc[4][3], sd4, p3);
                ffma2(acc[5][0], sd5, p0); ffma2(acc[5][1], sd5, p1);
                ffma2(acc[5][2], sd5, p2); ffma2(acc[5][3], sd5, p3);
                ffma2(acc[6][0], sd6, p0); ffma2(acc[6][1], sd6, p1);
                ffma2(acc[6][2], sd6, p2); ffma2(acc[6][3], sd6, p3);
                ffma2(acc[7][0], sd7, p0); ffma2(acc[7][1], sd7, p1);
                ffma2(acc[7][2], sd7, p2); ffma2(acc[7][3], sd7, p3);
            }
            // ---- chunk retirement ----
            const int n = it * NCHUNK + c;            // global chunk id
            if (lane == 0) {
                if (warp == 0) mbar_expect_tx(mb_full + f_st * 8, CH_BYTES); // arm n+3
                mbar_arrive_rank0(mb_empty + f_st * 8);                      // free stage
            }
            if (leader && mthread) {                  // issue chunk n+2
                const int m = n + 2;
                if (m < TOTALC) {
                    mbar_wait(mb_empty + e_st * 8, e_ph);
                    bulk_mc(sb + PST_OFF + e_st * CH_BYTES,
                            g_P + (m & (NCHUNK - 1)) * (CH_K * DP),
                            CH_BYTES, mb_full + e_st * 8, (uint16_t)0xFF);
                    if (++e_st == STAGES) { e_st = 0; e_ph ^= 1; }
                }
            }
            if (++f_st == STAGES) { f_st = 0; f_ph ^= 1; }
        }

        // ---- red write (R7 layout) ----
#pragma unroll
        for (int r = 0; r < 8; ++r) {
#pragma unroll
            for (int g = 0; g < 2; ++g) {
                float2 a = unpk(acc[r][2 * g]), b = unpk(acc[r][2 * g + 1]);
                float4 v; v.x = a.x; v.y = a.y; v.z = b.x; v.w = b.y;
                *(float4*)(redw + r * 256 + g * 128) = v;
            }
        }
        __syncthreads();

        // ================= epilogue: warp = row, lane col j = s*32+lane ======
        const int r = warp;
        float z[16];
#pragma unroll
        for (int s = 0; s < 16; ++s) {
            int j  = s * 32 + lane;
            int jc = j & 255, chj = j >> 8;
            const float* rb = redf + (chj * 4) * (8 * 256) + r * 256 + jc;
            float g = rb[0] + rb[2048] + rb[4096] + rb[6144];
            z[s] = g + q_reg[s];
        }

        if (it == ITERS) {
            const int gr = rowbase + r;
#pragma unroll
            for (int s = 0; s < 16; ++s) {
                int j = s * 32 + lane;
                if (j < D) out[gr * D + j] = z[s];
            }
            break;
        }

        float tp[16];
#pragma unroll
        for (int s = 0; s < 16; ++s)
            tp[s] = (2.f * z[s] - s_reg[s] - TWOSIG * y_reg[s]) * INVC;
        float part = 0.f;
#pragma unroll
        for (int s = 0; s < 16; ++s) {
            int j = s * 32 + lane;
            if (j >= NDIM && j < D - 1) part += tp[s] * tp[s];
        }
#pragma unroll
        for (int o = 16; o > 0; o >>= 1) part += __shfl_xor_sync(0xffffffffu, part, o);
        float nrm  = sqrtf(part);
        float tval = __shfl_sync(0xffffffffu, tp[15], 19);   // j=499 = 15*32+19
        float f3 = 0.5f * (tval + nrm);
        float fu = f3 / (nrm + 1e-12f);
        bool case1 = (nrm <= tval);
        bool case2 = (!case1) && (nrm <= -tval);
#pragma unroll
        for (int s = 0; s < 16; ++s) {
            int j = s * 32 + lane;
            float tk;
            if      (j < NDIM)   tk = tp[s];
            else if (j < D - 1)  tk = case1 ? tp[s] : (case2 ? 0.f : fu * tp[s]);
            else if (j == D - 1) tk = case1 ? tp[s] : (case2 ? 0.f : f3);
            else                 tk = 0.f;
            float sn = s_reg[s] + OMEGA * (tk - z[s]);
            s_reg[s] = sn;
            sdup[j * SROW + r] = dup2(sn);
        }
        __syncthreads();
    }
    CLUSTER_SYNC();   // no CTA exits while multicast traffic may target it
}

// ---------------- launch ----------------
extern "C" void kernel_launch(void* const* d_in, const int* in_sizes, int n_in,
                              void* d_out, int out_size) {
    const float* b    = (const float*)d_in[0];
    const float* c    = (const float*)d_in[1];
    const float* W1   = (const float*)d_in[2];
    const float* b1   = (const float*)d_in[3];
    const float* W2   = (const float*)d_in[4];
    const float* b2   = (const float*)d_in[5];
    const float* W3   = (const float*)d_in[6];
    const float* b3   = (const float*)d_in[7];
    const float* Aaug = (const float*)d_in[8];
    const float* Ainv = (const float*)d_in[9];
    float* out = (float*)d_out;

    void *p;
    cudaGetSymbolAddress(&p, g_h1); float* h1 = (float*)p;
    cudaGetSymbolAddress(&p, g_h2); float* h2 = (float*)p;
    cudaGetSymbolAddress(&p, g_y ); float* yy = (float*)p;
    cudaGetSymbolAddress(&p, g_q ); float* qq = (float*)p;

    computeP<<<(DP * DP) / 256, 256>>>(Aaug, Ainv);

    dim3 tb(16, 16);
    gemm16<<<dim3(HDIM / 16, BATCH / 16), tb>>>(b, c, W1, b1, h1, 500, HDIM, HDIM, FLAG_RELU | FLAG_CONCAT);
    gemm16<<<dim3(HDIM / 16, BATCH / 16), tb>>>(h1, nullptr, W2, b2, h2, HDIM, HDIM, HDIM, FLAG_RELU);
    gemm16<<<dim3(DP / 16, BATCH / 16), tb>>>(h2, nullptr, W3, b3, yy, HDIM, D, DP, 0);
    gemm16<<<dim3(DP / 16, BATCH / 16), tb>>>(b, nullptr, Ainv, nullptr, qq, MDIM, D, DP, FLAG_TRANSB);

    cudaFuncSetAttribute(iterate_kernel, cudaFuncAttributeMaxDynamicSharedMemorySize, SMEM_BYTES);
    iterate_kernel<<<BATCH / 8, 256, SMEM_BYTES>>>(out);
}